// round 2
// baseline (speedup 1.0000x reference)
#include <cuda_runtime.h>
#include <math.h>

#define Bv 4
#define Vv 8
#define Hh 128
#define Ww 128
#define Cc 64
#define HW (Hh*Ww)
#define NIMG (Bv*Vv)
#define VP (Vv-1)
#define NBJ (Bv*VP)

// Scratch (device globals: no allocation allowed in kernel_launch)
__device__ float g_feats[NIMG*Cc*HW];   // fused features, NCHW
__device__ float g_mid[NIMG*Cc*HW];     // gelu(conv1) output, NCHW
__device__ int   g_src[NBJ*HW];         // gather index or -1
__device__ float g_wgt[NBJ];            // GAMMA/hw * cnt
__device__ float g_cam[NBJ*16];         // M(3x4) = K*Einv[0:3], then Einv row2 (4)

// ---------------------------------------------------------------------------
// Kernel 1: per-(b,j) camera precompute. Full 4x4 inverse (adjugate), fold K.
// ---------------------------------------------------------------------------
__global__ void k_prep(const float* __restrict__ intr, const float* __restrict__ extr)
{
    int t = threadIdx.x;
    if (t >= NBJ) return;
    int b = t / VP, j = t % VP, k = j + 1;
    const float* E = extr + (b*Vv + k)*16;
    const float* K = intr + (b*Vv + k)*9;
    float m[16], inv[16];
    #pragma unroll
    for (int i = 0; i < 16; ++i) m[i] = E[i];

    inv[0]  =  m[5]*m[10]*m[15] - m[5]*m[11]*m[14] - m[9]*m[6]*m[15] + m[9]*m[7]*m[14] + m[13]*m[6]*m[11] - m[13]*m[7]*m[10];
    inv[4]  = -m[4]*m[10]*m[15] + m[4]*m[11]*m[14] + m[8]*m[6]*m[15] - m[8]*m[7]*m[14] - m[12]*m[6]*m[11] + m[12]*m[7]*m[10];
    inv[8]  =  m[4]*m[9]*m[15]  - m[4]*m[11]*m[13] - m[8]*m[5]*m[15] + m[8]*m[7]*m[13] + m[12]*m[5]*m[11] - m[12]*m[7]*m[9];
    inv[12] = -m[4]*m[9]*m[14]  + m[4]*m[10]*m[13] + m[8]*m[5]*m[14] - m[8]*m[6]*m[13] - m[12]*m[5]*m[10] + m[12]*m[6]*m[9];
    inv[1]  = -m[1]*m[10]*m[15] + m[1]*m[11]*m[14] + m[9]*m[2]*m[15] - m[9]*m[3]*m[14] - m[13]*m[2]*m[11] + m[13]*m[3]*m[10];
    inv[5]  =  m[0]*m[10]*m[15] - m[0]*m[11]*m[14] - m[8]*m[2]*m[15] + m[8]*m[3]*m[14] + m[12]*m[2]*m[11] - m[12]*m[3]*m[10];
    inv[9]  = -m[0]*m[9]*m[15]  + m[0]*m[11]*m[13] + m[8]*m[1]*m[15] - m[8]*m[3]*m[13] - m[12]*m[1]*m[11] + m[12]*m[3]*m[9];
    inv[13] =  m[0]*m[9]*m[14]  - m[0]*m[10]*m[13] - m[8]*m[1]*m[14] + m[8]*m[2]*m[13] + m[12]*m[1]*m[10] - m[12]*m[2]*m[9];
    inv[2]  =  m[1]*m[6]*m[15]  - m[1]*m[7]*m[14]  - m[5]*m[2]*m[15] + m[5]*m[3]*m[14] + m[13]*m[2]*m[7]  - m[13]*m[3]*m[6];
    inv[6]  = -m[0]*m[6]*m[15]  + m[0]*m[7]*m[14]  + m[4]*m[2]*m[15] - m[4]*m[3]*m[14] - m[12]*m[2]*m[7]  + m[12]*m[3]*m[6];
    inv[10] =  m[0]*m[5]*m[15]  - m[0]*m[7]*m[13]  - m[4]*m[1]*m[15] + m[4]*m[3]*m[13] + m[12]*m[1]*m[7]  - m[12]*m[3]*m[5];
    inv[14] = -m[0]*m[5]*m[14]  + m[0]*m[6]*m[13]  + m[4]*m[1]*m[14] - m[4]*m[2]*m[13] - m[12]*m[1]*m[6]  + m[12]*m[2]*m[5];
    inv[3]  = -m[1]*m[6]*m[11]  + m[1]*m[7]*m[10]  + m[5]*m[2]*m[11] - m[5]*m[3]*m[10] - m[9]*m[2]*m[7]   + m[9]*m[3]*m[6];
    inv[7]  =  m[0]*m[6]*m[11]  - m[0]*m[7]*m[10]  - m[4]*m[2]*m[11] + m[4]*m[3]*m[10] + m[8]*m[2]*m[7]   - m[8]*m[3]*m[6];
    inv[11] = -m[0]*m[5]*m[11]  + m[0]*m[7]*m[9]   + m[4]*m[1]*m[11] - m[4]*m[3]*m[9]  - m[8]*m[1]*m[7]   + m[8]*m[3]*m[5];
    inv[15] =  m[0]*m[5]*m[10]  - m[0]*m[6]*m[9]   - m[4]*m[1]*m[10] + m[4]*m[2]*m[9]  + m[8]*m[1]*m[6]   - m[8]*m[2]*m[5];

    float det = m[0]*inv[0] + m[1]*inv[4] + m[2]*inv[8] + m[3]*inv[12];
    float id = 1.0f / det;
    #pragma unroll
    for (int i = 0; i < 16; ++i) inv[i] *= id;

    float* o = g_cam + t*16;
    #pragma unroll
    for (int rr = 0; rr < 3; ++rr)
        #pragma unroll
        for (int c = 0; c < 4; ++c)
            o[rr*4 + c] = K[rr*3+0]*inv[0*4+c] + K[rr*3+1]*inv[1*4+c] + K[rr*3+2]*inv[2*4+c];
    #pragma unroll
    for (int c = 0; c < 4; ++c) o[12 + c] = inv[2*4 + c];
}

// ---------------------------------------------------------------------------
// Kernel 2: per-pixel projection -> gather index + mask count per (b,j)
// ---------------------------------------------------------------------------
__global__ void k_count(const float* __restrict__ means)
{
    int bj = blockIdx.x;
    int b = bj / VP, j = bj % VP;
    __shared__ float cm[16];
    __shared__ int s_cnt;
    if (threadIdx.x < 16) cm[threadIdx.x] = g_cam[bj*16 + threadIdx.x];
    if (threadIdx.x == 0) s_cnt = 0;
    __syncthreads();
    const float* mb = means + (size_t)(b*Vv + j)*HW*3;
    int cnt = 0;
    for (int i = threadIdx.x; i < HW; i += blockDim.x) {
        float x = mb[i*3+0], y = mb[i*3+1], z = mb[i*3+2];
        float cz = cm[12]*x + cm[13]*y + cm[14]*z + cm[15];
        float p0 = cm[0]*x + cm[1]*y + cm[2]*z  + cm[3];
        float p1 = cm[4]*x + cm[5]*y + cm[6]*z  + cm[7];
        float p2 = cm[8]*x + cm[9]*y + cm[10]*z + cm[11];
        float d  = p2 + 1e-8f;
        float nx = p0 / d, ny = p1 / d;
        bool valid = (nx >= 0.f) && (nx < 1.f) && (ny >= 0.f) && (ny < 1.f) && (cz > 1e-8f);
        int px = (int)floorf(nx * (float)Ww); px = min(max(px, 0), Ww-1);
        int py = (int)floorf(ny * (float)Hh); py = min(max(py, 0), Hh-1);
        g_src[bj*HW + i] = valid ? (py*Ww + px) : -1;
        cnt += valid ? 1 : 0;
    }
    atomicAdd(&s_cnt, cnt);
    __syncthreads();
    if (threadIdx.x == 0) g_wgt[bj] = (0.1f / (float)HW) * (float)s_cnt;
}

// ---------------------------------------------------------------------------
// Kernel 3: fuse + transpose NHWC->NCHW into g_feats.
// Block: (xseg, y, n), 256 threads, 64-pixel x segment, all 64 channels.
// ---------------------------------------------------------------------------
__global__ __launch_bounds__(256)
void k_fuse(const float* __restrict__ gsf)
{
    int xseg = blockIdx.x, y = blockIdx.y, n = blockIdx.z;
    int b = n >> 3, view = n & 7;
    int x0 = xseg * 64;
    __shared__ int   S[64];
    __shared__ float s_wv;
    __shared__ float comb[64*65];   // [c][px], pitch 65
    int tid = threadIdx.x;
    if (view < VP) {
        int bj = b*VP + view;
        if (tid < 64) S[tid] = g_src[bj*HW + y*Ww + x0 + tid];
        if (tid == 0) s_wv = g_wgt[bj];
    } else {
        if (tid < 64) S[tid] = -1;
        if (tid == 0) s_wv = 0.f;
    }
    __syncthreads();
    float wg = s_wv;
    float iw = 1.0f / (1.0f + wg);
    size_t fj = ((size_t)n*HW + (size_t)y*Ww + x0) * Cc;
    size_t fk = (size_t)(n+1) * HW * Cc;   // view k = view+1 (only deref'd when S>=0)
    #pragma unroll
    for (int it = 0; it < 4; ++it) {
        int px = (tid >> 4) + it*16;
        int c4 = (tid & 15) * 4;
        float4 a = *(const float4*)(gsf + fj + (size_t)px*Cc + c4);
        int s = S[px];
        float4 g = make_float4(0.f, 0.f, 0.f, 0.f);
        if (s >= 0) g = *(const float4*)(gsf + fk + (size_t)s*Cc + c4);
        float4 r;
        r.x = (a.x + g.x*wg) * iw;
        r.y = (a.y + g.y*wg) * iw;
        r.z = (a.z + g.z*wg) * iw;
        r.w = (a.w + g.w*wg) * iw;
        comb[(c4+0)*65 + px] = r.x;
        comb[(c4+1)*65 + px] = r.y;
        comb[(c4+2)*65 + px] = r.z;
        comb[(c4+3)*65 + px] = r.w;
    }
    __syncthreads();
    int x = tid & 63, cb = tid >> 6;
    #pragma unroll
    for (int k = 0; k < 16; ++k) {
        int c = cb*16 + k;
        g_feats[((n*Cc + c)*Hh + y)*Ww + x0 + x] = comb[c*65 + x];
    }
}

// ---------------------------------------------------------------------------
// Packed fp32x2 helpers (sm_100+ dual-FMA path)
// ---------------------------------------------------------------------------
__device__ __forceinline__ unsigned long long pk2(float lo, float hi) {
    unsigned long long r;
    asm("mov.b64 %0, {%1, %2};" : "=l"(r) : "f"(lo), "f"(hi));
    return r;
}
__device__ __forceinline__ void upk2(unsigned long long v, float& lo, float& hi) {
    asm("mov.b64 {%0, %1}, %2;" : "=f"(lo), "=f"(hi) : "l"(v));
}
__device__ __forceinline__ void fma2(unsigned long long& d, unsigned long long a, unsigned long long b) {
    asm("fma.rn.f32x2 %0, %1, %2, %0;" : "+l"(d) : "l"(a), "l"(b));
}

// ---------------------------------------------------------------------------
// Kernel 4/5: 3x3 SAME conv, NCHW in. Each thread: 8 oc x 8 px (4 f32x2 pairs).
// Block: 256 thr = 8 oc-groups x 32 px-threads; tile 16x16; ic chunks of 8.
// ---------------------------------------------------------------------------
template<bool GELU, bool NHWC_OUT>
__global__ __launch_bounds__(256)
void k_conv(const float* __restrict__ in, const float* __restrict__ w,
            const float* __restrict__ bias, float* __restrict__ out)
{
    __shared__ __align__(16) float s_in[8*18*19];   // [ic][yy 18][xx pitch 19]
    __shared__ __align__(16) float s_w[8*9*64];     // [ic][k][oc]
    int n  = blockIdx.z;
    int x0 = blockIdx.x * 16, y0 = blockIdx.y * 16;
    int tid = threadIdx.x;
    int ocg = tid >> 5;
    int t   = tid & 31;
    int rr  = t >> 1;            // row in tile 0..15
    int xh  = (t & 1) * 8;       // x sub-half 0 or 8

    unsigned long long acc[8][4];
    #pragma unroll
    for (int o = 0; o < 8; ++o)
        #pragma unroll
        for (int p = 0; p < 4; ++p) acc[o][p] = 0ULL;

    for (int ch = 0; ch < 8; ++ch) {
        if (ch) __syncthreads();
        for (int idx = tid; idx < 8*18*18; idx += 256) {
            int ic = idx / 324; int rem = idx - ic*324;
            int yy = rem / 18;  int xx = rem - yy*18;
            int gy = y0 + yy - 1, gx = x0 + xx - 1;
            float v = 0.f;
            if ((unsigned)gy < 128u && (unsigned)gx < 128u)
                v = in[((n*64 + ch*8 + ic)*128 + gy)*128 + gx];
            s_in[(ic*18 + yy)*19 + xx] = v;
        }
        for (int idx = tid; idx < 8*9*64; idx += 256) {
            int ic = idx / 576; int rem = idx - ic*576;
            int k = rem >> 6;   int oc = rem & 63;
            s_w[idx] = w[(oc*64 + ch*8 + ic)*9 + k];
        }
        __syncthreads();
        #pragma unroll
        for (int ic = 0; ic < 8; ++ic) {
            #pragma unroll
            for (int ky = 0; ky < 3; ++ky) {
                float v[10];
                const float* ip = &s_in[(ic*18 + rr + ky)*19 + xh];
                #pragma unroll
                for (int i = 0; i < 10; ++i) v[i] = ip[i];
                #pragma unroll
                for (int kx = 0; kx < 3; ++kx) {
                    const float4* wp = (const float4*)&s_w[(ic*9 + ky*3 + kx)*64 + ocg*8];
                    float4 wa = wp[0], wb = wp[1];
                    unsigned long long wd[8];
                    wd[0] = pk2(wa.x, wa.x); wd[1] = pk2(wa.y, wa.y);
                    wd[2] = pk2(wa.z, wa.z); wd[3] = pk2(wa.w, wa.w);
                    wd[4] = pk2(wb.x, wb.x); wd[5] = pk2(wb.y, wb.y);
                    wd[6] = pk2(wb.z, wb.z); wd[7] = pk2(wb.w, wb.w);
                    unsigned long long pr[4];
                    #pragma unroll
                    for (int p = 0; p < 4; ++p) pr[p] = pk2(v[2*p + kx], v[2*p + kx + 1]);
                    #pragma unroll
                    for (int o = 0; o < 8; ++o)
                        #pragma unroll
                        for (int p = 0; p < 4; ++p)
                            fma2(acc[o][p], wd[o], pr[p]);
                }
            }
        }
    }

    float bs[8];
    #pragma unroll
    for (int o = 0; o < 8; ++o) bs[o] = bias[ocg*8 + o];
    int oy = y0 + rr;
    #pragma unroll
    for (int p = 0; p < 4; ++p) {
        int ox = x0 + xh + p*2;
        float r0[8], r1[8];
        #pragma unroll
        for (int o = 0; o < 8; ++o) {
            float a, b2;
            upk2(acc[o][p], a, b2);
            a  += bs[o];
            b2 += bs[o];
            if (GELU) {
                a  = 0.5f * a  * (1.0f + erff(a  * 0.70710678118654752f));
                b2 = 0.5f * b2 * (1.0f + erff(b2 * 0.70710678118654752f));
            }
            r0[o] = a; r1[o] = b2;
        }
        if (!NHWC_OUT) {
            #pragma unroll
            for (int o = 0; o < 8; ++o) {
                float2 st = make_float2(r0[o], r1[o]);
                *(float2*)&out[((n*64 + ocg*8 + o)*128 + oy)*128 + ox] = st;
            }
        } else {
            size_t p0 = ((size_t)(n*128 + oy)*128 + ox)*64 + ocg*8;
            *(float4*)&out[p0]      = make_float4(r0[0], r0[1], r0[2], r0[3]);
            *(float4*)&out[p0 + 4]  = make_float4(r0[4], r0[5], r0[6], r0[7]);
            *(float4*)&out[p0 + 64] = make_float4(r1[0], r1[1], r1[2], r1[3]);
            *(float4*)&out[p0 + 68] = make_float4(r1[4], r1[5], r1[6], r1[7]);
        }
    }
}

// ---------------------------------------------------------------------------
extern "C" void kernel_launch(void* const* d_in, const int* in_sizes, int n_in,
                              void* d_out, int out_size)
{
    const float* means = (const float*)d_in[0];
    // d_in[1] = depths (unused)
    const float* gsf   = (const float*)d_in[2];
    const float* intr  = (const float*)d_in[3];
    const float* extr  = (const float*)d_in[4];
    const float* w1    = (const float*)d_in[5];
    const float* b1    = (const float*)d_in[6];
    const float* w2    = (const float*)d_in[7];
    const float* b2    = (const float*)d_in[8];
    float* out = (float*)d_out;

    float *pf = nullptr, *pm = nullptr;
    cudaGetSymbolAddress((void**)&pf, g_feats);
    cudaGetSymbolAddress((void**)&pm, g_mid);

    k_prep<<<1, 32>>>(intr, extr);
    k_count<<<NBJ, 256>>>(means);
    k_fuse<<<dim3(2, 128, 32), 256>>>(gsf);
    k_conv<true,  false><<<dim3(8, 8, 32), 256>>>(pf, w1, b1, pm);
    k_conv<false, true ><<<dim3(8, 8, 32), 256>>>(pm, w2, b2, out);
}

// round 3
// speedup vs baseline: 1.2837x; 1.2837x over previous
#include <cuda_runtime.h>
#include <math.h>

#define Bv 4
#define Vv 8
#define Hh 128
#define Ww 128
#define Cc 64
#define HW (Hh*Ww)
#define NIMG (Bv*Vv)
#define VP (Vv-1)
#define NBJ (Bv*VP)

__device__ float g_feats[NIMG*Cc*HW];   // fused features, NCHW
__device__ float g_mid[NIMG*Cc*HW];     // gelu(conv1), NCHW
__device__ int   g_src[NBJ*HW];
__device__ float g_wgt[NBJ];
__device__ float g_cam[NBJ*24];         // Einv rows0-2 (12) + K (9)

// ---------------------------------------------------------------------------
// Kernel 1: per-(b,j) camera precompute. Store Einv (rows 0-2) and K separately
// so the per-pixel math reproduces JAX's cam->proj sequence exactly.
// ---------------------------------------------------------------------------
__global__ void k_prep(const float* __restrict__ intr, const float* __restrict__ extr)
{
    int t = threadIdx.x;
    if (t >= NBJ) return;
    int b = t / VP, j = t % VP, k = j + 1;
    const float* E = extr + (b*Vv + k)*16;
    const float* K = intr + (b*Vv + k)*9;
    float m[16], inv[16];
    #pragma unroll
    for (int i = 0; i < 16; ++i) m[i] = E[i];

    inv[0]  =  m[5]*m[10]*m[15] - m[5]*m[11]*m[14] - m[9]*m[6]*m[15] + m[9]*m[7]*m[14] + m[13]*m[6]*m[11] - m[13]*m[7]*m[10];
    inv[4]  = -m[4]*m[10]*m[15] + m[4]*m[11]*m[14] + m[8]*m[6]*m[15] - m[8]*m[7]*m[14] - m[12]*m[6]*m[11] + m[12]*m[7]*m[10];
    inv[8]  =  m[4]*m[9]*m[15]  - m[4]*m[11]*m[13] - m[8]*m[5]*m[15] + m[8]*m[7]*m[13] + m[12]*m[5]*m[11] - m[12]*m[7]*m[9];
    inv[12] = -m[4]*m[9]*m[14]  + m[4]*m[10]*m[13] + m[8]*m[5]*m[14] - m[8]*m[6]*m[13] - m[12]*m[5]*m[10] + m[12]*m[6]*m[9];
    inv[1]  = -m[1]*m[10]*m[15] + m[1]*m[11]*m[14] + m[9]*m[2]*m[15] - m[9]*m[3]*m[14] - m[13]*m[2]*m[11] + m[13]*m[3]*m[10];
    inv[5]  =  m[0]*m[10]*m[15] - m[0]*m[11]*m[14] - m[8]*m[2]*m[15] + m[8]*m[3]*m[14] + m[12]*m[2]*m[11] - m[12]*m[3]*m[10];
    inv[9]  = -m[0]*m[9]*m[15]  + m[0]*m[11]*m[13] + m[8]*m[1]*m[15] - m[8]*m[3]*m[13] - m[12]*m[1]*m[11] + m[12]*m[3]*m[9];
    inv[13] =  m[0]*m[9]*m[14]  - m[0]*m[10]*m[13] - m[8]*m[1]*m[14] + m[8]*m[2]*m[13] + m[12]*m[1]*m[10] - m[12]*m[2]*m[9];
    inv[2]  =  m[1]*m[6]*m[15]  - m[1]*m[7]*m[14]  - m[5]*m[2]*m[15] + m[5]*m[3]*m[14] + m[13]*m[2]*m[7]  - m[13]*m[3]*m[6];
    inv[6]  = -m[0]*m[6]*m[15]  + m[0]*m[7]*m[14]  + m[4]*m[2]*m[15] - m[4]*m[3]*m[14] - m[12]*m[2]*m[7]  + m[12]*m[3]*m[6];
    inv[10] =  m[0]*m[5]*m[15]  - m[0]*m[7]*m[13]  - m[4]*m[1]*m[15] + m[4]*m[3]*m[13] + m[12]*m[1]*m[7]  - m[12]*m[3]*m[5];
    inv[14] = -m[0]*m[5]*m[14]  + m[0]*m[6]*m[13]  + m[4]*m[1]*m[14] - m[4]*m[2]*m[13] - m[12]*m[1]*m[6]  + m[12]*m[2]*m[5];
    inv[3]  = -m[1]*m[6]*m[11]  + m[1]*m[7]*m[10]  + m[5]*m[2]*m[11] - m[5]*m[3]*m[10] - m[9]*m[2]*m[7]   + m[9]*m[3]*m[6];
    inv[7]  =  m[0]*m[6]*m[11]  - m[0]*m[7]*m[10]  - m[4]*m[2]*m[11] + m[4]*m[3]*m[10] + m[8]*m[2]*m[7]   - m[8]*m[3]*m[6];
    inv[11] = -m[0]*m[5]*m[11]  + m[0]*m[7]*m[9]   + m[4]*m[1]*m[11] - m[4]*m[3]*m[9]  - m[8]*m[1]*m[7]   + m[8]*m[3]*m[5];
    inv[15] =  m[0]*m[5]*m[10]  - m[0]*m[6]*m[9]   - m[4]*m[1]*m[10] + m[4]*m[2]*m[9]  + m[8]*m[1]*m[6]   - m[8]*m[2]*m[5];

    float det = m[0]*inv[0] + m[1]*inv[4] + m[2]*inv[8] + m[3]*inv[12];
    float id = 1.0f / det;
    #pragma unroll
    for (int i = 0; i < 16; ++i) inv[i] *= id;

    float* o = g_cam + t*24;
    #pragma unroll
    for (int i = 0; i < 12; ++i) o[i] = inv[i];
    #pragma unroll
    for (int i = 0; i < 9; ++i) o[12 + i] = K[i];
}

// ---------------------------------------------------------------------------
// Kernel 2: projection -> gather index + mask count. Mirrors JAX rounding:
// cam = Einv*[p,1]; proj = K*cam (plain mul/add, no fma contraction); ndc.
// ---------------------------------------------------------------------------
__global__ void k_count(const float* __restrict__ means)
{
    int bj = blockIdx.x;
    int b = bj / VP, j = bj % VP;
    __shared__ float cm[24];
    __shared__ int s_cnt;
    if (threadIdx.x < 24) cm[threadIdx.x] = g_cam[bj*24 + threadIdx.x];
    if (threadIdx.x == 0) s_cnt = 0;
    __syncthreads();
    const float* mb = means + (size_t)(b*Vv + j)*HW*3;
    int cnt = 0;
    for (int i = threadIdx.x; i < HW; i += blockDim.x) {
        float x = mb[i*3+0], y = mb[i*3+1], z = mb[i*3+2];
        float c0 = __fadd_rn(__fadd_rn(__fadd_rn(__fmul_rn(cm[0],x), __fmul_rn(cm[1],y)), __fmul_rn(cm[2],z)), cm[3]);
        float c1 = __fadd_rn(__fadd_rn(__fadd_rn(__fmul_rn(cm[4],x), __fmul_rn(cm[5],y)), __fmul_rn(cm[6],z)), cm[7]);
        float c2 = __fadd_rn(__fadd_rn(__fadd_rn(__fmul_rn(cm[8],x), __fmul_rn(cm[9],y)), __fmul_rn(cm[10],z)), cm[11]);
        float p0 = __fadd_rn(__fadd_rn(__fmul_rn(cm[12],c0), __fmul_rn(cm[13],c1)), __fmul_rn(cm[14],c2));
        float p1 = __fadd_rn(__fadd_rn(__fmul_rn(cm[15],c0), __fmul_rn(cm[16],c1)), __fmul_rn(cm[17],c2));
        float p2 = __fadd_rn(__fadd_rn(__fmul_rn(cm[18],c0), __fmul_rn(cm[19],c1)), __fmul_rn(cm[20],c2));
        float d  = __fadd_rn(p2, 1e-8f);
        float nx = p0 / d, ny = p1 / d;
        bool valid = (nx >= 0.f) && (nx < 1.f) && (ny >= 0.f) && (ny < 1.f) && (c2 > 1e-8f);
        int px = (int)floorf(__fmul_rn(nx, (float)Ww)); px = min(max(px, 0), Ww-1);
        int py = (int)floorf(__fmul_rn(ny, (float)Hh)); py = min(max(py, 0), Hh-1);
        g_src[bj*HW + i] = valid ? (py*Ww + px) : -1;
        cnt += valid ? 1 : 0;
    }
    atomicAdd(&s_cnt, cnt);
    __syncthreads();
    if (threadIdx.x == 0) g_wgt[bj] = (0.1f / (float)HW) * (float)s_cnt;
}

// ---------------------------------------------------------------------------
// Kernel 3: fuse + transpose NHWC->NCHW into g_feats.
// ---------------------------------------------------------------------------
__global__ __launch_bounds__(256)
void k_fuse(const float* __restrict__ gsf)
{
    int xseg = blockIdx.x, y = blockIdx.y, n = blockIdx.z;
    int b = n >> 3, view = n & 7;
    int x0 = xseg * 64;
    __shared__ int   S[64];
    __shared__ float s_wv;
    __shared__ float comb[64*65];
    int tid = threadIdx.x;
    if (view < VP) {
        int bj = b*VP + view;
        if (tid < 64) S[tid] = g_src[bj*HW + y*Ww + x0 + tid];
        if (tid == 0) s_wv = g_wgt[bj];
    } else {
        if (tid < 64) S[tid] = -1;
        if (tid == 0) s_wv = 0.f;
    }
    __syncthreads();
    float wg = s_wv;
    float iw = 1.0f / (1.0f + wg);
    size_t fj = ((size_t)n*HW + (size_t)y*Ww + x0) * Cc;
    size_t fk = (size_t)(n+1) * HW * Cc;
    #pragma unroll
    for (int it = 0; it < 4; ++it) {
        int px = (tid >> 4) + it*16;
        int c4 = (tid & 15) * 4;
        float4 a = *(const float4*)(gsf + fj + (size_t)px*Cc + c4);
        int s = S[px];
        float4 g = make_float4(0.f, 0.f, 0.f, 0.f);
        if (s >= 0) g = *(const float4*)(gsf + fk + (size_t)s*Cc + c4);
        float4 r;
        r.x = (a.x + g.x*wg) * iw;
        r.y = (a.y + g.y*wg) * iw;
        r.z = (a.z + g.z*wg) * iw;
        r.w = (a.w + g.w*wg) * iw;
        comb[(c4+0)*65 + px] = r.x;
        comb[(c4+1)*65 + px] = r.y;
        comb[(c4+2)*65 + px] = r.z;
        comb[(c4+3)*65 + px] = r.w;
    }
    __syncthreads();
    int x = tid & 63, cb = tid >> 6;
    #pragma unroll
    for (int k = 0; k < 16; ++k) {
        int c = cb*16 + k;
        g_feats[((n*Cc + c)*Hh + y)*Ww + x0 + x] = comb[c*65 + x];
    }
}

// ---------------------------------------------------------------------------
// Packed fp32x2 helpers
// ---------------------------------------------------------------------------
typedef unsigned long long ull;
__device__ __forceinline__ ull pk2(float lo, float hi) {
    ull r;
    asm("mov.b64 %0, {%1, %2};" : "=l"(r) : "f"(lo), "f"(hi));
    return r;
}
__device__ __forceinline__ void upk2(ull v, float& lo, float& hi) {
    asm("mov.b64 {%0, %1}, %2;" : "=f"(lo), "=f"(hi) : "l"(v));
}
__device__ __forceinline__ void fma2(ull& d, ull a, ull b) {
    asm("fma.rn.f32x2 %0, %1, %2, %0;" : "+l"(d) : "l"(a), "l"(b));
}

// ---------------------------------------------------------------------------
// Kernel 4/5: 3x3 SAME conv, NCHW in. Weight-stationary (8 oc per block),
// f32x2 packed over OC-PAIRS (weight pairs load directly as LDS.64 broadcast,
// no duplication MOVs). Tile 32x32 px, ic chunked by 2, double-buffered input.
// Thread: 4 consecutive px x 4 oc-pairs (all 8 oc). 256 threads.
// ---------------------------------------------------------------------------
#define PITCH 35
template<bool GELU, bool NHWC_OUT>
__global__ __launch_bounds__(256, 3)
void k_conv(const float* __restrict__ in, const float* __restrict__ w,
            const float* __restrict__ bias, float* __restrict__ out)
{
    __shared__ float s_w[64*9*8];            // [ic][tap][oc_local] 18432B
    __shared__ float s_in[2*2*34*PITCH];     // [buf][ic][row34][PITCH] 19040B

    int ocg = blockIdx.x;            // 8 consecutive blocks share input tile
    int tile = blockIdx.y;
    int n    = blockIdx.z;
    int x0 = (tile & 3) * 32, y0 = (tile >> 2) * 32;
    int oc0 = ocg * 8;
    int tid = threadIdx.x;
    int prow = tid >> 3;             // 0..31
    int xg   = (tid & 7) * 4;        // 0,4,...,28

    // Load stationary weights: s_w[(ic*9+tap)*8 + ocl] = w[(oc0+ocl)*576 + ic*9 + tap]
    #pragma unroll
    for (int i = 0; i < 18; ++i) {
        int idx = tid + i*256;       // 0..4607
        int ict = idx >> 3, ocl = idx & 7;   // ict = ic*9+tap
        int ic = ict / 9, tap = ict - ic*9;
        s_w[idx] = w[(oc0 + ocl)*576 + ic*9 + tap];
    }

    const float* inb = in + (size_t)n*64*HW;

    // Load chunk 0 (ic 0,1) into buffer 0
    #pragma unroll
    for (int i = 0; i < 10; ++i) {
        int idx = tid + i*256;
        if (idx < 2312) {
            int ic = idx / 1156; int rem = idx - ic*1156;
            int rr = rem / 34, cc = rem - rr*34;
            int gy = y0 + rr - 1, gx = x0 + cc - 1;
            float v = 0.f;
            if ((unsigned)gy < 128u && (unsigned)gx < 128u)
                v = inb[(ic*128 + gy)*128 + gx];
            s_in[(ic*34 + rr)*PITCH + cc] = v;
        }
    }
    __syncthreads();

    ull acc[4][4];   // [oc_pair][px]
    #pragma unroll
    for (int o = 0; o < 4; ++o)
        #pragma unroll
        for (int p = 0; p < 4; ++p) acc[o][p] = 0ULL;

    #pragma unroll 1
    for (int ch = 0; ch < 32; ++ch) {
        // Prefetch next chunk into registers
        float pf[10];
        if (ch < 31) {
            int icb = (ch + 1) * 2;
            #pragma unroll
            for (int i = 0; i < 10; ++i) {
                int idx = tid + i*256;
                pf[i] = 0.f;
                if (idx < 2312) {
                    int ic = idx / 1156; int rem = idx - ic*1156;
                    int rr = rem / 34, cc = rem - rr*34;
                    int gy = y0 + rr - 1, gx = x0 + cc - 1;
                    if ((unsigned)gy < 128u && (unsigned)gx < 128u)
                        pf[i] = inb[((icb + ic)*128 + gy)*128 + gx];
                }
            }
        }
        // Compute on current buffer
        const float* sb = &s_in[(ch & 1) * (2*34*PITCH)];
        #pragma unroll
        for (int ic = 0; ic < 2; ++ic) {
            int icg = ch*2 + ic;
            #pragma unroll
            for (int ky = 0; ky < 3; ++ky) {
                const float* ip = &sb[(ic*34 + prow + ky)*PITCH + xg];
                float v0 = ip[0], v1 = ip[1], v2 = ip[2], v3 = ip[3], v4 = ip[4], v5 = ip[5];
                ull d0 = pk2(v0,v0), d1 = pk2(v1,v1), d2 = pk2(v2,v2);
                ull d3 = pk2(v3,v3), d4 = pk2(v4,v4), d5 = pk2(v5,v5);
                #pragma unroll
                for (int kx = 0; kx < 3; ++kx) {
                    const ull* wp = (const ull*)&s_w[(icg*9 + ky*3 + kx)*8];
                    ull w0 = wp[0], w1 = wp[1], w2 = wp[2], w3 = wp[3];
                    ull e0 = (kx==0) ? d0 : (kx==1) ? d1 : d2;
                    ull e1 = (kx==0) ? d1 : (kx==1) ? d2 : d3;
                    ull e2 = (kx==0) ? d2 : (kx==1) ? d3 : d4;
                    ull e3 = (kx==0) ? d3 : (kx==1) ? d4 : d5;
                    fma2(acc[0][0], w0, e0); fma2(acc[0][1], w0, e1);
                    fma2(acc[0][2], w0, e2); fma2(acc[0][3], w0, e3);
                    fma2(acc[1][0], w1, e0); fma2(acc[1][1], w1, e1);
                    fma2(acc[1][2], w1, e2); fma2(acc[1][3], w1, e3);
                    fma2(acc[2][0], w2, e0); fma2(acc[2][1], w2, e1);
                    fma2(acc[2][2], w2, e2); fma2(acc[2][3], w2, e3);
                    fma2(acc[3][0], w3, e0); fma2(acc[3][1], w3, e1);
                    fma2(acc[3][2], w3, e2); fma2(acc[3][3], w3, e3);
                }
            }
        }
        // Commit prefetched chunk into the other buffer
        if (ch < 31) {
            float* sn = &s_in[((ch + 1) & 1) * (2*34*PITCH)];
            #pragma unroll
            for (int i = 0; i < 10; ++i) {
                int idx = tid + i*256;
                if (idx < 2312) {
                    int ic = idx / 1156; int rem = idx - ic*1156;
                    int rr = rem / 34, cc = rem - rr*34;
                    sn[(ic*34 + rr)*PITCH + cc] = pf[i];
                }
            }
            __syncthreads();
        }
    }

    // Epilogue
    float r[8][4];
    #pragma unroll
    for (int o = 0; o < 4; ++o)
        #pragma unroll
        for (int p = 0; p < 4; ++p)
            upk2(acc[o][p], r[2*o][p], r[2*o+1][p]);
    #pragma unroll
    for (int o = 0; o < 8; ++o) {
        float bv = bias[oc0 + o];
        #pragma unroll
        for (int p = 0; p < 4; ++p) {
            float a = r[o][p] + bv;
            if (GELU) a = 0.5f * a * (1.0f + erff(a * 0.70710678118654752f));
            r[o][p] = a;
        }
    }
    int gy = y0 + prow, gx = x0 + xg;
    if (!NHWC_OUT) {
        #pragma unroll
        for (int o = 0; o < 8; ++o)
            *(float4*)&out[(((size_t)n*64 + oc0 + o)*128 + gy)*128 + gx] =
                make_float4(r[o][0], r[o][1], r[o][2], r[o][3]);
    } else {
        #pragma unroll
        for (int p = 0; p < 4; ++p) {
            size_t p0 = ((size_t)(n*HW) + (size_t)gy*128 + gx + p)*64 + oc0;
            *(float4*)&out[p0]     = make_float4(r[0][p], r[1][p], r[2][p], r[3][p]);
            *(float4*)&out[p0 + 4] = make_float4(r[4][p], r[5][p], r[6][p], r[7][p]);
        }
    }
}

// ---------------------------------------------------------------------------
extern "C" void kernel_launch(void* const* d_in, const int* in_sizes, int n_in,
                              void* d_out, int out_size)
{
    const float* means = (const float*)d_in[0];
    const float* gsf   = (const float*)d_in[2];
    const float* intr  = (const float*)d_in[3];
    const float* extr  = (const float*)d_in[4];
    const float* w1    = (const float*)d_in[5];
    const float* b1    = (const float*)d_in[6];
    const float* w2    = (const float*)d_in[7];
    const float* b2    = (const float*)d_in[8];
    float* out = (float*)d_out;

    float *pf = nullptr, *pm = nullptr;
    cudaGetSymbolAddress((void**)&pf, g_feats);
    cudaGetSymbolAddress((void**)&pm, g_mid);

    k_prep<<<1, 32>>>(intr, extr);
    k_count<<<NBJ, 256>>>(means);
    k_fuse<<<dim3(2, 128, 32), 256>>>(gsf);
    k_conv<true,  false><<<dim3(8, 16, 32), 256>>>(pf, w1, b1, pm);
    k_conv<false, true ><<<dim3(8, 16, 32), 256>>>(pm, w2, b2, out);
}